// round 2
// baseline (speedup 1.0000x reference)
#include <cuda_runtime.h>
#include <cstdint>

#define NEXP 8
#define NTOK 8192
#define H    2048
#define I2   4096   /* 2*I, rows of w1 per expert */
#define ID   2048   /* I */
#define MAXTILES 136
#define PADSLOTS (MAXTILES*128)

// ---------------- device scratch (static, no runtime alloc) ----------------
__device__ int    g_count[NEXP];
__device__ int    g_offset[NEXP];
__device__ int    g_ntiles;
__device__ int    g_tile_e[MAXTILES];
__device__ int    g_tile_s[MAXTILES];
__device__ int    g_tok[NEXP*NTOK];     // token*2+k codes, per-expert lists
__device__ int    g_slot[NTOK*2];       // (token,k) -> compacted slot
__device__ float2 g_wv[NTOK];           // routing weights (w0,w1)
__device__ __align__(16) float g_xg[(size_t)PADSLOTS*H];   // gathered activations
__device__ __align__(16) float g_y [(size_t)PADSLOTS*ID];  // swiglu output
__device__ __align__(16) float g_ob[(size_t)PADSLOTS*H];   // per-slot expert output

// ---------------- init ----------------
__global__ void k_init() {
    if (threadIdx.x < NEXP) g_count[threadIdx.x] = 0;
}

// ---------------- gating: one warp per token ----------------
__global__ void k_gate(const float* __restrict__ x, const float* __restrict__ gw,
                       const float* __restrict__ gb) {
    int warp = (blockIdx.x * blockDim.x + threadIdx.x) >> 5;
    int lane = threadIdx.x & 31;
    if (warp >= NTOK) return;
    const float* xr = x + (size_t)warp * H;
    float acc[NEXP];
#pragma unroll
    for (int e = 0; e < NEXP; e++) acc[e] = 0.f;
    for (int i = lane; i < H; i += 32) {
        float xv = xr[i];
#pragma unroll
        for (int e = 0; e < NEXP; e++) acc[e] += xv * gw[e*H + i];
    }
#pragma unroll
    for (int e = 0; e < NEXP; e++) {
#pragma unroll
        for (int o = 16; o > 0; o >>= 1) acc[e] += __shfl_xor_sync(0xffffffffu, acc[e], o);
    }
    if (lane == 0) {
        float lg[NEXP];
#pragma unroll
        for (int e = 0; e < NEXP; e++) lg[e] = acc[e] + gb[e];
        int b0 = 0;
#pragma unroll
        for (int e = 1; e < NEXP; e++) if (lg[e] > lg[b0]) b0 = e;   // first max = lowest idx on tie
        int b1 = -1;
#pragma unroll
        for (int e = 0; e < NEXP; e++) {
            if (e == b0) continue;
            if (b1 < 0 || lg[e] > lg[b1]) b1 = e;
        }
        float e1 = expf(lg[b1] - lg[b0]);
        float inv = 1.f / (1.f + e1);
        g_wv[warp] = make_float2(inv, e1 * inv);
        int p0 = atomicAdd(&g_count[b0], 1);
        g_tok[b0*NTOK + p0] = warp*2 + 0;
        int p1 = atomicAdd(&g_count[b1], 1);
        g_tok[b1*NTOK + p1] = warp*2 + 1;
    }
}

// ---------------- scan: offsets + tile table ----------------
__global__ void k_scan() {
    if (threadIdx.x == 0) {
        int base = 0, nt = 0;
        for (int e = 0; e < NEXP; e++) {
            g_offset[e] = base;
            int c = g_count[e];
            int t = (c + 127) >> 7;
            for (int i = 0; i < t; i++) { g_tile_e[nt] = e; g_tile_s[nt] = base + i*128; nt++; }
            base += t * 128;
        }
        g_ntiles = nt;
    }
}

// ---------------- gather: compact x rows per expert, record slot map ----------------
__global__ void k_gather(const float* __restrict__ x) {
    int e    = blockIdx.x;
    int pos0 = blockIdx.y * 8;
    int cnt  = g_count[e];
    if (pos0 >= cnt) return;
    int off = g_offset[e];
    for (int r = 0; r < 8; r++) {
        int pos = pos0 + r;
        if (pos >= cnt) break;
        int code = g_tok[e*NTOK + pos];
        int t    = code >> 1;
        int slot = off + pos;
        if (threadIdx.x == 0) g_slot[code] = slot;
        const float4* src = (const float4*)(x + (size_t)t * H);
        float4*       dst = (float4*)(g_xg + (size_t)slot * H);
        for (int i = threadIdx.x; i < H/4; i += blockDim.x) dst[i] = src[i];
    }
}

// ---------------- GEMM core: C(128x128) = A(128xK) * W(128xK)^T ----------------
// SWIGLU=true : A=g_xg, W=w1[e] rows n0..n0+127, fused bias+SwiGLU -> g_y
// SWIGLU=false: A=g_y,  W=w2[e] rows n0..n0+127, bias              -> g_ob
template<bool SWIGLU>
__global__ __launch_bounds__(256, 2) void k_gemm(const float* __restrict__ Wbase,
                                                 const float* __restrict__ Bbase) {
    int tile = blockIdx.x;
    if (tile >= g_ntiles) return;
    const int Nrows = SWIGLU ? I2 : H;
    int e     = g_tile_e[tile];
    int sbase = g_tile_s[tile];
    int n0    = blockIdx.y * 128;
    const float* A  = (SWIGLU ? g_xg : g_y) + (size_t)sbase * H;
    const float* W  = Wbase + (size_t)e * Nrows * H + (size_t)n0 * H;
    const float* bs = Bbase + (size_t)e * Nrows + n0;

    __shared__ __align__(16) float As[16][132];
    __shared__ __align__(16) float Bs[16][132];
    int tid = threadIdx.x;
    int tm = (tid >> 4) << 3, tn = (tid & 15) << 3;
    float c[8][8];
#pragma unroll
    for (int i = 0; i < 8; i++)
#pragma unroll
        for (int j = 0; j < 8; j++) c[i][j] = 0.f;

    for (int k0 = 0; k0 < H; k0 += 16) {
#pragma unroll
        for (int i = 0; i < 2; i++) {
            int f4 = tid*2 + i;               // 0..511: 128 rows x 4 float4
            int row = f4 >> 2, kq = (f4 & 3) << 2;
            float4 va = *(const float4*)(A + (size_t)row*H + k0 + kq);
            As[kq+0][row]=va.x; As[kq+1][row]=va.y; As[kq+2][row]=va.z; As[kq+3][row]=va.w;
            float4 vb = *(const float4*)(W + (size_t)row*H + k0 + kq);
            Bs[kq+0][row]=vb.x; Bs[kq+1][row]=vb.y; Bs[kq+2][row]=vb.z; Bs[kq+3][row]=vb.w;
        }
        __syncthreads();
#pragma unroll
        for (int kk = 0; kk < 16; kk++) {
            float a[8], b[8];
            *(float4*)(a)   = *(const float4*)&As[kk][tm];
            *(float4*)(a+4) = *(const float4*)&As[kk][tm+4];
            *(float4*)(b)   = *(const float4*)&Bs[kk][tn];
            *(float4*)(b+4) = *(const float4*)&Bs[kk][tn+4];
#pragma unroll
            for (int i = 0; i < 8; i++)
#pragma unroll
                for (int j = 0; j < 8; j++) c[i][j] += a[i] * b[j];
        }
        __syncthreads();
    }

    if (SWIGLU) {
        // columns tn..tn+7 are consecutive and even-aligned -> glu/lin pairs are thread-local
#pragma unroll
        for (int i = 0; i < 8; i++) {
            int slot = sbase + tm + i;
            float* yr = g_y + (size_t)slot * ID + ((n0 + tn) >> 1);
#pragma unroll
            for (int p = 0; p < 4; p++) {
                float glu = c[i][2*p]   + bs[tn + 2*p];
                float lin = c[i][2*p+1] + bs[tn + 2*p + 1];
                float s = 1.f / (1.f + expf(-1.702f * glu));
                yr[p] = glu * s * (lin + 1.f);
            }
        }
    } else {
#pragma unroll
        for (int i = 0; i < 8; i++) {
            int slot = sbase + tm + i;
            float* orow = g_ob + (size_t)slot * H + n0 + tn;
#pragma unroll
            for (int j = 0; j < 8; j++) orow[j] = c[i][j] + bs[tn + j];
        }
    }
}

// ---------------- combine: out[t] = w0*ob[slot0] + w1*ob[slot1] ----------------
__global__ void k_comb(float* __restrict__ out) {
    int gid = blockIdx.x * blockDim.x + threadIdx.x;   // one float4 each
    if (gid >= NTOK * (H/4)) return;
    int t = gid / (H/4), c4 = gid % (H/4);
    int s0 = g_slot[2*t], s1 = g_slot[2*t + 1];
    float2 w = g_wv[t];
    float4 a = *((const float4*)(g_ob + (size_t)s0 * H) + c4);
    float4 b = *((const float4*)(g_ob + (size_t)s1 * H) + c4);
    float4 r;
    r.x = w.x*a.x + w.y*b.x;
    r.y = w.x*a.y + w.y*b.y;
    r.z = w.x*a.z + w.y*b.z;
    r.w = w.x*a.w + w.y*b.w;
    *((float4*)out + gid) = r;
}

// ---------------- launcher ----------------
extern "C" void kernel_launch(void* const* d_in, const int* in_sizes, int n_in,
                              void* d_out, int out_size) {
    const float* x  = (const float*)d_in[0];
    const float* gw = (const float*)d_in[1];
    const float* gb = (const float*)d_in[2];
    const float* w1 = (const float*)d_in[3];
    const float* b1 = (const float*)d_in[4];
    const float* w2 = (const float*)d_in[5];
    const float* b2 = (const float*)d_in[6];
    float* out = (float*)d_out;

    k_init<<<1, 32>>>();
    k_gate<<<NTOK/8, 256>>>(x, gw, gb);
    k_scan<<<1, 32>>>();
    k_gather<<<dim3(NEXP, NTOK/8), 256>>>(x);
    k_gemm<true ><<<dim3(MAXTILES, I2/128), 256>>>(w1, b1);
    k_gemm<false><<<dim3(MAXTILES, H /128), 256>>>(w2, b2);
    k_comb<<<(NTOK*(H/4) + 255)/256, 256>>>(out);
}